// round 14
// baseline (speedup 1.0000x reference)
#include <cuda_runtime.h>
#include <cstdint>

// KNN entropy estimator — cluster/DSMEM form with ASYMMETRIC slabs.
//   mc_c = (k+1)-th largest of column c
//   sum_i eps = 2*S_c - N*mc - corr(top6) - N*max(mc,0)   (clippers are in the top-6)
//   H = C(k) + (1/N) * sum_c colv_c,  C(k) = gamma - H_{k-1} + digamma(16) + 15/k
//
// One cluster of 8 CTAs x 512 thr. 128-row units: rank0 takes 3 units, ranks
// 1..6 take 2, rank7 takes 1 (total 16 = 2048 rows). Rank 0's extra compute
// hides the publishers' DSMEM push + arrive + try_wait wakeup (~300 cyc that
// R13 left exposed after rank 0's equal-size slab finished). Per-slab top-6 is
// still exact (any slab contributes at most 6 of the global top-6).
// Handshake: st.shared::cluster.v4 push + release mbarrier arrive; rank 0
// try_waits once (HW sleep — R11: active polling throttles incoming pushes).

#define NN   2048
#define DD   16
#define NCTA 8
#define TPB  512
#define CST  388             // padded column stride (384 rows + 4); 388%32==4 (swizzle-safe)
#define RSL  132             // record slab stride in floats (528 B)
#define NARR (7 * 16)        // arrivals: ranks 1..7, one per warp
#define NEGF (-1e30f)

__device__ __forceinline__ void ce(float& a, float& b) {   // descending comparator
    float h = fmaxf(a, b), l = fminf(a, b); a = h; b = l;
}

// Optimal 6-element sorting network (12 CE, depth 5), descending.
__device__ __forceinline__ void sort6(float t[6]) {
    ce(t[0],t[5]); ce(t[1],t[3]); ce(t[2],t[4]);
    ce(t[1],t[2]); ce(t[3],t[4]);
    ce(t[0],t[3]); ce(t[2],t[5]);
    ce(t[0],t[1]); ce(t[2],t[3]); ce(t[4],t[5]);
    ce(t[1],t[2]); ce(t[3],t[4]);
}

// Merge two descending 6-lists, keep top-6 (bitonic split + sort6).
__device__ __forceinline__ void merge6(float t[6], const float o[6]) {
    t[0]=fmaxf(t[0],o[5]); t[1]=fmaxf(t[1],o[4]); t[2]=fmaxf(t[2],o[3]);
    t[3]=fmaxf(t[3],o[2]); t[4]=fmaxf(t[4],o[1]); t[5]=fmaxf(t[5],o[0]);
    sort6(t);
}

// Batcher sort8 (19 CE, depth 6), descending; writes top-6 into t.
__device__ __forceinline__ void sort8_top6(float t[6], float4 ga, float4 gb) {
    float v0=ga.x, v1=ga.y, v2=ga.z, v3=ga.w, v4=gb.x, v5=gb.y, v6=gb.z, v7=gb.w;
    ce(v0,v1); ce(v2,v3); ce(v4,v5); ce(v6,v7);
    ce(v0,v2); ce(v1,v3); ce(v4,v6); ce(v5,v7);
    ce(v1,v2); ce(v5,v6);
    ce(v0,v4); ce(v1,v5); ce(v2,v6); ce(v3,v7);
    ce(v2,v4); ce(v3,v5);
    ce(v1,v2); ce(v3,v4); ce(v5,v6);
    t[0]=v0; t[1]=v1; t[2]=v2; t[3]=v3; t[4]=v4; t[5]=v5;
}

__device__ __forceinline__ void sort4_list(float t[6], float4 g) {   // sort4 -> 6-list
    ce(g.x, g.z); ce(g.y, g.w); ce(g.x, g.y); ce(g.z, g.w); ce(g.y, g.z);
    t[0]=g.x; t[1]=g.y; t[2]=g.z; t[3]=g.w; t[4]=NEGF; t[5]=NEGF;
}

template<int FIRST_OFF>
__device__ __forceinline__ void shfl_merge6(float t[6]) {
#pragma unroll
    for (int off = FIRST_OFF; off >= 1; off >>= 1) {
        float o[6];
#pragma unroll
        for (int e = 0; e < 6; e++)
            o[e] = __shfl_down_sync(0xffffffffu, t[e], off);
        merge6(t, o);
    }
}

__device__ __forceinline__ uint32_t smem_u32(const void* p) {
    uint32_t a;
    asm("{ .reg .u64 t; cvta.to.shared.u64 t, %1; cvt.u32.u64 %0, t; }"
        : "=r"(a) : "l"(p));
    return a;
}

extern "C" __global__ void __launch_bounds__(TPB, 1)
__cluster_dims__(NCTA, 1, 1)
knn_entropy_kernel(const float* __restrict__ x,
                   const int* __restrict__ kptr,
                   float* __restrict__ out) {
    __shared__ __align__(16) float sxt[DD * CST];    // transposed slab (swizzled rows)
    __shared__ __align__(16) float recs[NCTA * RSL]; // rank0: incoming records
    __shared__ __align__(8)  unsigned long long mbar;
    __shared__ float colv[DD];

    const int tid  = threadIdx.x;
    const int w    = tid >> 5;
    const int lane = tid & 31;
    uint32_t rank;
    asm("mov.u32 %0, %%cluster_ctarank;" : "=r"(rank));

    const int k = __ldg(kptr);

    // ---- Asymmetric unit assignment: rank0=3, ranks1-6=2, rank7=1 (128-row units) ----
    const int cnt   = (rank == 0) ? 3 : ((rank == 7) ? 1 : 2);
    const int start = (rank == 0) ? 0 : (2 * (int)rank + 1);

    // ---- Issue slab loads: one float4/thread per unit ----
    const float4* x4 = (const float4*)x + start * 512;
    float4 f0 = x4[tid];
    float4 f1, f2;
    if (cnt >= 2) f1 = x4[tid + 512];
    if (cnt >= 3) f2 = x4[tid + 1024];

    // ---- mbarrier init + full cluster.sync UNDER THE LOAD SHADOW ----
    const uint32_t mb = smem_u32(&mbar);
    if (rank == 0 && tid == 0) {
        asm volatile("mbarrier.init.shared.b64 [%0], %1;" :: "r"(mb), "r"(NARR) : "memory");
        asm volatile("fence.mbarrier_init.release.cluster;" ::: "memory");
    }
    asm volatile("barrier.cluster.arrive.aligned;" ::: "memory");
    asm volatile("barrier.cluster.wait.aligned;"  ::: "memory");

    // ---- Transpose into SMEM, XOR-8 row swizzle (conflict-free, 388%32==4) ----
    {
        const int c0 = (tid & 3) << 2;
        const int row = ((tid >> 2) ^ (c0 & 8));     // unit-local swizzled row
        sxt[(c0+0)*CST + row] = f0.x; sxt[(c0+1)*CST + row] = f0.y;
        sxt[(c0+2)*CST + row] = f0.z; sxt[(c0+3)*CST + row] = f0.w;
        if (cnt >= 2) {
            sxt[(c0+0)*CST + row+128] = f1.x; sxt[(c0+1)*CST + row+128] = f1.y;
            sxt[(c0+2)*CST + row+128] = f1.z; sxt[(c0+3)*CST + row+128] = f1.w;
        }
        if (cnt >= 3) {
            sxt[(c0+0)*CST + row+256] = f2.x; sxt[(c0+1)*CST + row+256] = f2.y;
            sxt[(c0+2)*CST + row+256] = f2.z; sxt[(c0+3)*CST + row+256] = f2.w;
        }
    }
    __syncthreads();

    // ---- Warp w: slab top-6 + sum of column w (4*cnt vals/lane) ----
    const float4* colq = (const float4*)(sxt + w * CST);
    const int li = lane ^ ((w & 8) >> 2);            // swizzle-compensating lane perm
    float t[6];
    float s;
    {
        float4 ga = colq[li];
        s = (ga.x + ga.y) + (ga.z + ga.w);
        if (cnt == 1) {
            sort4_list(t, ga);
        } else {
            float4 gb = colq[li + 32];
            s += (gb.x + gb.y) + (gb.z + gb.w);
            sort8_top6(t, ga, gb);
            if (cnt >= 3) {
                float4 gc = colq[li + 64];
                s += (gc.x + gc.y) + (gc.z + gc.w);
                float o[6];
                sort4_list(o, gc);
                merge6(t, o);
            }
        }
    }

    shfl_merge6<16>(t);
#pragma unroll
    for (int off = 16; off >= 1; off >>= 1)
        s += __shfl_down_sync(0xffffffffu, s, off);
    // lane 0 holds this slab's (top6, S) for column w

    if (rank != 0) {
        if (lane == 0) {    // push record into rank0's SMEM, then release-arrive
            uint32_t loc = smem_u32(&recs[rank * RSL + w * 8]);
            uint32_t dst, rmb;
            asm("mapa.shared::cluster.u32 %0, %1, 0;" : "=r"(dst) : "r"(loc));
            asm("mapa.shared::cluster.u32 %0, %1, 0;" : "=r"(rmb) : "r"(mb));
            asm volatile("st.shared::cluster.v4.f32 [%0], {%1,%2,%3,%4};"
                         :: "r"(dst), "f"(t[0]), "f"(t[1]), "f"(t[2]), "f"(t[3]) : "memory");
            asm volatile("st.shared::cluster.v4.f32 [%0], {%1,%2,%3,%4};"
                         :: "r"(dst + 16), "f"(t[4]), "f"(t[5]), "f"(s), "f"(0.0f) : "memory");
            asm volatile("mbarrier.arrive.release.cluster.shared::cluster.b64 _, [%0];"
                         :: "r"(rmb) : "memory");
        }
        return;
    }

    // ================= rank 0: try_wait once (HW sleep), then combine =========
    {
        uint32_t done;
        asm volatile(
            "{\n\t"
            ".reg .pred p;\n\t"
            "WL_%=:\n\t"
            "mbarrier.try_wait.parity.acquire.cluster.shared::cta.b64 p, [%1], %2, 0x989680;\n\t"
            "@p bra WD_%=;\n\t"
            "bra WL_%=;\n\t"
            "WD_%=:\n\t"
            "mov.u32 %0, 1;\n\t"
            "}"
            : "=r"(done) : "r"(mb), "r"(0) : "memory");
        (void)done;
    }

    // Warp w merges its own record (lane 0, in regs) + 7 pushed records.
    float t2[6];
    float s2;
    if (lane == 0) {
#pragma unroll
        for (int e = 0; e < 6; e++) t2[e] = t[e];
        s2 = s;
    } else if (lane < NCTA) {          // conflict-free: bank = (4*lane + 8w) % 32
        const float4* r4 = (const float4*)&recs[lane * RSL + w * 8];
        float4 ra = r4[0], rb = r4[1];
        t2[0]=ra.x; t2[1]=ra.y; t2[2]=ra.z; t2[3]=ra.w;
        t2[4]=rb.x; t2[5]=rb.y; s2 = rb.z;
    } else {
#pragma unroll
        for (int e = 0; e < 6; e++) t2[e] = NEGF;
        s2 = 0.0f;
    }

    shfl_merge6<4>(t2);
#pragma unroll
    for (int off = 4; off >= 1; off >>= 1)
        s2 += __shfl_down_sync(0xffffffffu, s2, off);

    if (lane == 0) {
        const int kk = k < 1 ? 1 : (k > 5 ? 5 : k);   // mc index = kk within top-6
        float mc = t2[kk];
        const float tau = 0.5f * (1.0f + mc);
        float corr = 0.0f;
#pragma unroll
        for (int e = 0; e < 6; e++)
            if (t2[e] > tau) corr += 2.0f * t2[e] - mc - 1.0f;
        colv[w] = 2.0f * s2 - (float)NN * mc - corr - (float)NN * fmaxf(mc, 0.0f);
    }
    __syncthreads();

    if (w == 0) {
        float a = (lane < DD) ? colv[lane] : 0.0f;
#pragma unroll
        for (int off = 8; off >= 1; off >>= 1)
            a += __shfl_down_sync(0xffffffffu, a, off);
        if (lane == 0) {
            // C(k) = gamma - H_{k-1} + digamma(16) + 15/k (double-precomputed,
            // selected into a register, no memory access).
            float C = (k <= 1) ? 18.31822899f :
                      (k == 2) ?  9.81822899f :
                      (k == 3) ?  6.81822899f :
                      (k == 4) ?  5.23489566f :
                      (k == 5) ?  4.23489566f :
                                  3.53489566f;        // k >= 6
            out[0] = C + a * (1.0f / (float)NN);
        }
    }
}

extern "C" void kernel_launch(void* const* d_in, const int* in_sizes, int n_in,
                              void* d_out, int out_size) {
    // metadata order: x [N*D f32], k [1 i32] — pick by size to be robust.
    int xi = 0, ki = 1;
    if (n_in >= 2 && in_sizes[0] == 1) { xi = 1; ki = 0; }
    const float* x    = (const float*)d_in[xi];
    const int*   kptr = (const int*)d_in[ki];
    float*       out  = (float*)d_out;

    knn_entropy_kernel<<<NCTA, TPB>>>(x, kptr, out);
}

// round 15
// speedup vs baseline: 1.0349x; 1.0349x over previous
#include <cuda_runtime.h>
#include <cstdint>

// KNN entropy estimator — cluster/DSMEM form, asymmetric slabs v2 (4/2/2/2/2/2/1/1).
//   mc_c = (k+1)-th largest of column c
//   sum_i eps = 2*S_c - N*mc - corr(top6) - N*max(mc,0)   (clippers are in the top-6)
//   H = C(k) + (1/N) * sum_c colv_c,  C(k) = gamma - H_{k-1} + digamma(16) + 15/k
//
// One cluster of 8 CTAs x 512 thr, 128-row units: rank0=4, ranks1-5=2,
// ranks6-7=1 (total 16 = 2048 rows). Rank 0's extra compute (2x sort8 +
// merge6) fully hides the publishers' DSMEM push (~215cyc) + arrive, so its
// try_wait takes the fast path. Per-slab top-6 stays exact. Handshake:
// st.shared::cluster.v4 push + release mbarrier arrive; rank 0 try_waits once
// (HW sleep — R11: active polling throttles the incoming pushes).

#define NN   2048
#define DD   16
#define NCTA 8
#define TPB  512
#define CST  516             // padded column stride (512 rows + 4); 516%32==4 (swizzle-safe)
#define RSL  132             // record slab stride in floats (528 B)
#define NARR (7 * 16)        // arrivals: ranks 1..7, one per warp
#define NEGF (-1e30f)

__device__ __forceinline__ void ce(float& a, float& b) {   // descending comparator
    float h = fmaxf(a, b), l = fminf(a, b); a = h; b = l;
}

// Optimal 6-element sorting network (12 CE, depth 5), descending.
__device__ __forceinline__ void sort6(float t[6]) {
    ce(t[0],t[5]); ce(t[1],t[3]); ce(t[2],t[4]);
    ce(t[1],t[2]); ce(t[3],t[4]);
    ce(t[0],t[3]); ce(t[2],t[5]);
    ce(t[0],t[1]); ce(t[2],t[3]); ce(t[4],t[5]);
    ce(t[1],t[2]); ce(t[3],t[4]);
}

// Merge two descending 6-lists, keep top-6 (bitonic split + sort6).
__device__ __forceinline__ void merge6(float t[6], const float o[6]) {
    t[0]=fmaxf(t[0],o[5]); t[1]=fmaxf(t[1],o[4]); t[2]=fmaxf(t[2],o[3]);
    t[3]=fmaxf(t[3],o[2]); t[4]=fmaxf(t[4],o[1]); t[5]=fmaxf(t[5],o[0]);
    sort6(t);
}

// Batcher sort8 (19 CE, depth 6), descending; writes top-6 into t.
__device__ __forceinline__ void sort8_top6(float t[6], float4 ga, float4 gb) {
    float v0=ga.x, v1=ga.y, v2=ga.z, v3=ga.w, v4=gb.x, v5=gb.y, v6=gb.z, v7=gb.w;
    ce(v0,v1); ce(v2,v3); ce(v4,v5); ce(v6,v7);
    ce(v0,v2); ce(v1,v3); ce(v4,v6); ce(v5,v7);
    ce(v1,v2); ce(v5,v6);
    ce(v0,v4); ce(v1,v5); ce(v2,v6); ce(v3,v7);
    ce(v2,v4); ce(v3,v5);
    ce(v1,v2); ce(v3,v4); ce(v5,v6);
    t[0]=v0; t[1]=v1; t[2]=v2; t[3]=v3; t[4]=v4; t[5]=v5;
}

__device__ __forceinline__ void sort4_list(float t[6], float4 g) {   // sort4 -> 6-list
    ce(g.x, g.z); ce(g.y, g.w); ce(g.x, g.y); ce(g.z, g.w); ce(g.y, g.z);
    t[0]=g.x; t[1]=g.y; t[2]=g.z; t[3]=g.w; t[4]=NEGF; t[5]=NEGF;
}

template<int FIRST_OFF>
__device__ __forceinline__ void shfl_merge6(float t[6]) {
#pragma unroll
    for (int off = FIRST_OFF; off >= 1; off >>= 1) {
        float o[6];
#pragma unroll
        for (int e = 0; e < 6; e++)
            o[e] = __shfl_down_sync(0xffffffffu, t[e], off);
        merge6(t, o);
    }
}

__device__ __forceinline__ uint32_t smem_u32(const void* p) {
    uint32_t a;
    asm("{ .reg .u64 t; cvta.to.shared.u64 t, %1; cvt.u32.u64 %0, t; }"
        : "=r"(a) : "l"(p));
    return a;
}

extern "C" __global__ void __launch_bounds__(TPB, 1)
__cluster_dims__(NCTA, 1, 1)
knn_entropy_kernel(const float* __restrict__ x,
                   const int* __restrict__ kptr,
                   float* __restrict__ out) {
    __shared__ __align__(16) float sxt[DD * CST];    // transposed slab (swizzled rows)
    __shared__ __align__(16) float recs[NCTA * RSL]; // rank0: incoming records
    __shared__ __align__(8)  unsigned long long mbar;
    __shared__ float colv[DD];

    const int tid  = threadIdx.x;
    const int w    = tid >> 5;
    const int lane = tid & 31;
    uint32_t rank;
    asm("mov.u32 %0, %%cluster_ctarank;" : "=r"(rank));

    const int k = __ldg(kptr);

    // ---- Asymmetric unit assignment (128-row units, 16 total):
    //      rank0: units 0-3 | ranks1-5: 2 units (4+2(r-1)) | rank6: 14 | rank7: 15
    const int cnt   = (rank == 0) ? 4 : ((rank >= 6) ? 1 : 2);
    const int start = (rank == 0) ? 0 : ((rank >= 6) ? (8 + (int)rank) : (2 * (int)rank + 2));

    // ---- Issue slab loads: one float4/thread per unit ----
    const float4* x4 = (const float4*)x + start * 512;
    float4 f0 = x4[tid];
    float4 f1, f2, f3;
    if (cnt >= 2) f1 = x4[tid + 512];
    if (cnt >= 4) { f2 = x4[tid + 1024]; f3 = x4[tid + 1536]; }

    // ---- mbarrier init + full cluster.sync UNDER THE LOAD SHADOW ----
    const uint32_t mb = smem_u32(&mbar);
    if (rank == 0 && tid == 0) {
        asm volatile("mbarrier.init.shared.b64 [%0], %1;" :: "r"(mb), "r"(NARR) : "memory");
        asm volatile("fence.mbarrier_init.release.cluster;" ::: "memory");
    }
    asm volatile("barrier.cluster.arrive.aligned;" ::: "memory");
    asm volatile("barrier.cluster.wait.aligned;"  ::: "memory");

    // ---- Transpose into SMEM, XOR-8 row swizzle (conflict-free, 516%32==4) ----
    {
        const int c0 = (tid & 3) << 2;
        const int row = ((tid >> 2) ^ (c0 & 8));     // unit-local swizzled row
        sxt[(c0+0)*CST + row] = f0.x; sxt[(c0+1)*CST + row] = f0.y;
        sxt[(c0+2)*CST + row] = f0.z; sxt[(c0+3)*CST + row] = f0.w;
        if (cnt >= 2) {
            sxt[(c0+0)*CST + row+128] = f1.x; sxt[(c0+1)*CST + row+128] = f1.y;
            sxt[(c0+2)*CST + row+128] = f1.z; sxt[(c0+3)*CST + row+128] = f1.w;
        }
        if (cnt >= 4) {
            sxt[(c0+0)*CST + row+256] = f2.x; sxt[(c0+1)*CST + row+256] = f2.y;
            sxt[(c0+2)*CST + row+256] = f2.z; sxt[(c0+3)*CST + row+256] = f2.w;
            sxt[(c0+0)*CST + row+384] = f3.x; sxt[(c0+1)*CST + row+384] = f3.y;
            sxt[(c0+2)*CST + row+384] = f3.z; sxt[(c0+3)*CST + row+384] = f3.w;
        }
    }
    __syncthreads();

    // ---- Warp w: slab top-6 + sum of column w (4*cnt vals/lane) ----
    const float4* colq = (const float4*)(sxt + w * CST);
    const int li = lane ^ ((w & 8) >> 2);            // swizzle-compensating lane perm
    float t[6];
    float s;
    {
        float4 ga = colq[li];
        s = (ga.x + ga.y) + (ga.z + ga.w);
        if (cnt == 1) {
            sort4_list(t, ga);
        } else {
            float4 gb = colq[li + 32];
            s += (gb.x + gb.y) + (gb.z + gb.w);
            sort8_top6(t, ga, gb);
            if (cnt >= 4) {
                float4 gc = colq[li + 64];
                float4 gd = colq[li + 96];
                s += (gc.x + gc.y) + (gc.z + gc.w);
                s += (gd.x + gd.y) + (gd.z + gd.w);
                float o[6];
                sort8_top6(o, gc, gd);
                merge6(t, o);
            }
        }
    }

    shfl_merge6<16>(t);
#pragma unroll
    for (int off = 16; off >= 1; off >>= 1)
        s += __shfl_down_sync(0xffffffffu, s, off);
    // lane 0 holds this slab's (top6, S) for column w

    if (rank != 0) {
        if (lane == 0) {    // push record into rank0's SMEM, then release-arrive
            uint32_t loc = smem_u32(&recs[rank * RSL + w * 8]);
            uint32_t dst, rmb;
            asm("mapa.shared::cluster.u32 %0, %1, 0;" : "=r"(dst) : "r"(loc));
            asm("mapa.shared::cluster.u32 %0, %1, 0;" : "=r"(rmb) : "r"(mb));
            asm volatile("st.shared::cluster.v4.f32 [%0], {%1,%2,%3,%4};"
                         :: "r"(dst), "f"(t[0]), "f"(t[1]), "f"(t[2]), "f"(t[3]) : "memory");
            asm volatile("st.shared::cluster.v4.f32 [%0], {%1,%2,%3,%4};"
                         :: "r"(dst + 16), "f"(t[4]), "f"(t[5]), "f"(s), "f"(0.0f) : "memory");
            asm volatile("mbarrier.arrive.release.cluster.shared::cluster.b64 _, [%0];"
                         :: "r"(rmb) : "memory");
        }
        return;
    }

    // ================= rank 0: try_wait once (HW sleep), then combine =========
    {
        uint32_t done;
        asm volatile(
            "{\n\t"
            ".reg .pred p;\n\t"
            "WL_%=:\n\t"
            "mbarrier.try_wait.parity.acquire.cluster.shared::cta.b64 p, [%1], %2, 0x989680;\n\t"
            "@p bra WD_%=;\n\t"
            "bra WL_%=;\n\t"
            "WD_%=:\n\t"
            "mov.u32 %0, 1;\n\t"
            "}"
            : "=r"(done) : "r"(mb), "r"(0) : "memory");
        (void)done;
    }

    // Warp w merges its own record (lane 0, in regs) + 7 pushed records.
    float t2[6];
    float s2;
    if (lane == 0) {
#pragma unroll
        for (int e = 0; e < 6; e++) t2[e] = t[e];
        s2 = s;
    } else if (lane < NCTA) {          // conflict-free: bank = (4*lane + 8w) % 32
        const float4* r4 = (const float4*)&recs[lane * RSL + w * 8];
        float4 ra = r4[0], rb = r4[1];
        t2[0]=ra.x; t2[1]=ra.y; t2[2]=ra.z; t2[3]=ra.w;
        t2[4]=rb.x; t2[5]=rb.y; s2 = rb.z;
    } else {
#pragma unroll
        for (int e = 0; e < 6; e++) t2[e] = NEGF;
        s2 = 0.0f;
    }

    shfl_merge6<4>(t2);
#pragma unroll
    for (int off = 4; off >= 1; off >>= 1)
        s2 += __shfl_down_sync(0xffffffffu, s2, off);

    if (lane == 0) {
        const int kk = k < 1 ? 1 : (k > 5 ? 5 : k);   // mc index = kk within top-6
        float mc = t2[kk];
        const float tau = 0.5f * (1.0f + mc);
        float corr = 0.0f;
#pragma unroll
        for (int e = 0; e < 6; e++)
            if (t2[e] > tau) corr += 2.0f * t2[e] - mc - 1.0f;
        colv[w] = 2.0f * s2 - (float)NN * mc - corr - (float)NN * fmaxf(mc, 0.0f);
    }
    __syncthreads();

    if (w == 0) {
        float a = (lane < DD) ? colv[lane] : 0.0f;
#pragma unroll
        for (int off = 8; off >= 1; off >>= 1)
            a += __shfl_down_sync(0xffffffffu, a, off);
        if (lane == 0) {
            // C(k) = gamma - H_{k-1} + digamma(16) + 15/k (double-precomputed,
            // selected into a register, no memory access).
            float C = (k <= 1) ? 18.31822899f :
                      (k == 2) ?  9.81822899f :
                      (k == 3) ?  6.81822899f :
                      (k == 4) ?  5.23489566f :
                      (k == 5) ?  4.23489566f :
                                  3.53489566f;        // k >= 6
            out[0] = C + a * (1.0f / (float)NN);
        }
    }
}

extern "C" void kernel_launch(void* const* d_in, const int* in_sizes, int n_in,
                              void* d_out, int out_size) {
    // metadata order: x [N*D f32], k [1 i32] — pick by size to be robust.
    int xi = 0, ki = 1;
    if (n_in >= 2 && in_sizes[0] == 1) { xi = 1; ki = 0; }
    const float* x    = (const float*)d_in[xi];
    const int*   kptr = (const int*)d_in[ki];
    float*       out  = (float*)d_out;

    knn_entropy_kernel<<<NCTA, TPB>>>(x, kptr, out);
}

// round 17
// speedup vs baseline: 1.0389x; 1.0039x over previous
#include <cuda_runtime.h>
#include <cstdint>

// KNN entropy estimator — FINAL: cluster/DSMEM form, asymmetric slabs (4/2/2/2/2/2/1/1).
//
// Algorithmic collapse of the O(N^2*D) reference:
//   kth-smallest_j (x[i,c]-x[j,c]) = x[i,c] - mc_c,  mc_c = (k+1)-th largest of col c
//   lo = max(mc,0) (x-independent);  clippers (2x-mc>1) are inside the top-6, so
//   sum_i eps = 2*S_c - N*mc - corr(top6) - N*max(mc,0)
//   H = C(k) + (1/N) * sum_c colv_c,  C(k) = gamma - H_{k-1} + digamma(16) + 15/k
//
// One cluster of 8 CTAs x 512 thr, 128-row units: rank0=4, ranks1-5=2,
// ranks6-7=1. Rank 0's extra compute hides the publishers' DSMEM push
// (~215cyc) + arrive, so its try_wait takes the fast path. Handshake:
// st.shared::cluster.v4 push + release mbarrier arrive; rank 0 try_waits once
// (HW sleep — active SMEM polling throttles the incoming pushes, R11).
// Transpose uses an XOR-8 row swizzle (conflict-free STS at stride%32==4).
// Selection: Batcher sort8 networks + bitonic-split top-6 merges (no serial
// insert chains); digamma tail is double-precomputed register immediates.

#define NN   2048
#define DD   16
#define NCTA 8
#define TPB  512
#define CST  516             // padded column stride (512 rows + 4); 516%32==4 (swizzle-safe)
#define RSL  132             // record slab stride in floats (528 B)
#define NARR (7 * 16)        // arrivals: ranks 1..7, one per warp
#define NEGF (-1e30f)

__device__ __forceinline__ void ce(float& a, float& b) {   // descending comparator
    float h = fmaxf(a, b), l = fminf(a, b); a = h; b = l;
}

// Optimal 6-element sorting network (12 CE, depth 5), descending.
__device__ __forceinline__ void sort6(float t[6]) {
    ce(t[0],t[5]); ce(t[1],t[3]); ce(t[2],t[4]);
    ce(t[1],t[2]); ce(t[3],t[4]);
    ce(t[0],t[3]); ce(t[2],t[5]);
    ce(t[0],t[1]); ce(t[2],t[3]); ce(t[4],t[5]);
    ce(t[1],t[2]); ce(t[3],t[4]);
}

// Merge two descending 6-lists, keep top-6 (bitonic split + sort6).
__device__ __forceinline__ void merge6(float t[6], const float o[6]) {
    t[0]=fmaxf(t[0],o[5]); t[1]=fmaxf(t[1],o[4]); t[2]=fmaxf(t[2],o[3]);
    t[3]=fmaxf(t[3],o[2]); t[4]=fmaxf(t[4],o[1]); t[5]=fmaxf(t[5],o[0]);
    sort6(t);
}

// Batcher sort8 (19 CE, depth 6), descending; writes top-6 into t.
__device__ __forceinline__ void sort8_top6(float t[6], float4 ga, float4 gb) {
    float v0=ga.x, v1=ga.y, v2=ga.z, v3=ga.w, v4=gb.x, v5=gb.y, v6=gb.z, v7=gb.w;
    ce(v0,v1); ce(v2,v3); ce(v4,v5); ce(v6,v7);
    ce(v0,v2); ce(v1,v3); ce(v4,v6); ce(v5,v7);
    ce(v1,v2); ce(v5,v6);
    ce(v0,v4); ce(v1,v5); ce(v2,v6); ce(v3,v7);
    ce(v2,v4); ce(v3,v5);
    ce(v1,v2); ce(v3,v4); ce(v5,v6);
    t[0]=v0; t[1]=v1; t[2]=v2; t[3]=v3; t[4]=v4; t[5]=v5;
}

__device__ __forceinline__ void sort4_list(float t[6], float4 g) {   // sort4 -> 6-list
    ce(g.x, g.z); ce(g.y, g.w); ce(g.x, g.y); ce(g.z, g.w); ce(g.y, g.z);
    t[0]=g.x; t[1]=g.y; t[2]=g.z; t[3]=g.w; t[4]=NEGF; t[5]=NEGF;
}

template<int FIRST_OFF>
__device__ __forceinline__ void shfl_merge6(float t[6]) {
#pragma unroll
    for (int off = FIRST_OFF; off >= 1; off >>= 1) {
        float o[6];
#pragma unroll
        for (int e = 0; e < 6; e++)
            o[e] = __shfl_down_sync(0xffffffffu, t[e], off);
        merge6(t, o);
    }
}

__device__ __forceinline__ uint32_t smem_u32(const void* p) {
    uint32_t a;
    asm("{ .reg .u64 t; cvta.to.shared.u64 t, %1; cvt.u32.u64 %0, t; }"
        : "=r"(a) : "l"(p));
    return a;
}

extern "C" __global__ void __launch_bounds__(TPB, 1)
__cluster_dims__(NCTA, 1, 1)
knn_entropy_kernel(const float* __restrict__ x,
                   const int* __restrict__ kptr,
                   float* __restrict__ out) {
    __shared__ __align__(16) float sxt[DD * CST];    // transposed slab (swizzled rows)
    __shared__ __align__(16) float recs[NCTA * RSL]; // rank0: incoming records
    __shared__ __align__(8)  unsigned long long mbar;
    __shared__ float colv[DD];

    const int tid  = threadIdx.x;
    const int w    = tid >> 5;
    const int lane = tid & 31;
    uint32_t rank;
    asm("mov.u32 %0, %%cluster_ctarank;" : "=r"(rank));

    const int k = __ldg(kptr);

    // ---- Asymmetric unit assignment (128-row units, 16 total):
    //      rank0: units 0-3 | ranks1-5: 2 units (4+2(r-1)) | rank6: 14 | rank7: 15
    const int cnt   = (rank == 0) ? 4 : ((rank >= 6) ? 1 : 2);
    const int start = (rank == 0) ? 0 : ((rank >= 6) ? (8 + (int)rank) : (2 * (int)rank + 2));

    // ---- Issue slab loads: one float4/thread per unit ----
    const float4* x4 = (const float4*)x + start * 512;
    float4 f0 = x4[tid];
    float4 f1, f2, f3;
    if (cnt >= 2) f1 = x4[tid + 512];
    if (cnt >= 4) { f2 = x4[tid + 1024]; f3 = x4[tid + 1536]; }

    // ---- mbarrier init + full cluster.sync UNDER THE LOAD SHADOW ----
    const uint32_t mb = smem_u32(&mbar);
    if (rank == 0 && tid == 0) {
        asm volatile("mbarrier.init.shared.b64 [%0], %1;" :: "r"(mb), "r"(NARR) : "memory");
        asm volatile("fence.mbarrier_init.release.cluster;" ::: "memory");
    }
    asm volatile("barrier.cluster.arrive.aligned;" ::: "memory");
    asm volatile("barrier.cluster.wait.aligned;"  ::: "memory");

    // ---- Transpose into SMEM, XOR-8 row swizzle (conflict-free, 516%32==4) ----
    {
        const int c0 = (tid & 3) << 2;
        const int row = ((tid >> 2) ^ (c0 & 8));     // unit-local swizzled row
        sxt[(c0+0)*CST + row] = f0.x; sxt[(c0+1)*CST + row] = f0.y;
        sxt[(c0+2)*CST + row] = f0.z; sxt[(c0+3)*CST + row] = f0.w;
        if (cnt >= 2) {
            sxt[(c0+0)*CST + row+128] = f1.x; sxt[(c0+1)*CST + row+128] = f1.y;
            sxt[(c0+2)*CST + row+128] = f1.z; sxt[(c0+3)*CST + row+128] = f1.w;
        }
        if (cnt >= 4) {
            sxt[(c0+0)*CST + row+256] = f2.x; sxt[(c0+1)*CST + row+256] = f2.y;
            sxt[(c0+2)*CST + row+256] = f2.z; sxt[(c0+3)*CST + row+256] = f2.w;
            sxt[(c0+0)*CST + row+384] = f3.x; sxt[(c0+1)*CST + row+384] = f3.y;
            sxt[(c0+2)*CST + row+384] = f3.z; sxt[(c0+3)*CST + row+384] = f3.w;
        }
    }
    __syncthreads();

    // ---- Warp w: slab top-6 + sum of column w (4*cnt vals/lane) ----
    const float4* colq = (const float4*)(sxt + w * CST);
    const int li = lane ^ ((w & 8) >> 2);            // swizzle-compensating lane perm
    float t[6];
    float s;
    {
        float4 ga = colq[li];
        s = (ga.x + ga.y) + (ga.z + ga.w);
        if (cnt == 1) {
            sort4_list(t, ga);
        } else {
            float4 gb = colq[li + 32];
            s += (gb.x + gb.y) + (gb.z + gb.w);
            sort8_top6(t, ga, gb);
            if (cnt >= 4) {
                float4 gc = colq[li + 64];
                float4 gd = colq[li + 96];
                s += (gc.x + gc.y) + (gc.z + gc.w);
                s += (gd.x + gd.y) + (gd.z + gd.w);
                float o[6];
                sort8_top6(o, gc, gd);
                merge6(t, o);
            }
        }
    }

    shfl_merge6<16>(t);
#pragma unroll
    for (int off = 16; off >= 1; off >>= 1)
        s += __shfl_down_sync(0xffffffffu, s, off);
    // lane 0 holds this slab's (top6, S) for column w

    if (rank != 0) {
        if (lane == 0) {    // push record into rank0's SMEM, then release-arrive
            uint32_t loc = smem_u32(&recs[rank * RSL + w * 8]);
            uint32_t dst, rmb;
            asm("mapa.shared::cluster.u32 %0, %1, 0;" : "=r"(dst) : "r"(loc));
            asm("mapa.shared::cluster.u32 %0, %1, 0;" : "=r"(rmb) : "r"(mb));
            asm volatile("st.shared::cluster.v4.f32 [%0], {%1,%2,%3,%4};"
                         :: "r"(dst), "f"(t[0]), "f"(t[1]), "f"(t[2]), "f"(t[3]) : "memory");
            asm volatile("st.shared::cluster.v4.f32 [%0], {%1,%2,%3,%4};"
                         :: "r"(dst + 16), "f"(t[4]), "f"(t[5]), "f"(s), "f"(0.0f) : "memory");
            asm volatile("mbarrier.arrive.release.cluster.shared::cluster.b64 _, [%0];"
                         :: "r"(rmb) : "memory");
        }
        return;
    }

    // ================= rank 0: try_wait once (HW sleep), then combine =========
    {
        uint32_t done;
        asm volatile(
            "{\n\t"
            ".reg .pred p;\n\t"
            "WL_%=:\n\t"
            "mbarrier.try_wait.parity.acquire.cluster.shared::cta.b64 p, [%1], %2, 0x989680;\n\t"
            "@p bra WD_%=;\n\t"
            "bra WL_%=;\n\t"
            "WD_%=:\n\t"
            "mov.u32 %0, 1;\n\t"
            "}"
            : "=r"(done) : "r"(mb), "r"(0) : "memory");
        (void)done;
    }

    // Warp w merges its own record (lane 0, in regs) + 7 pushed records.
    float t2[6];
    float s2;
    if (lane == 0) {
#pragma unroll
        for (int e = 0; e < 6; e++) t2[e] = t[e];
        s2 = s;
    } else if (lane < NCTA) {          // conflict-free: bank = (4*lane + 8w) % 32
        const float4* r4 = (const float4*)&recs[lane * RSL + w * 8];
        float4 ra = r4[0], rb = r4[1];
        t2[0]=ra.x; t2[1]=ra.y; t2[2]=ra.z; t2[3]=ra.w;
        t2[4]=rb.x; t2[5]=rb.y; s2 = rb.z;
    } else {
#pragma unroll
        for (int e = 0; e < 6; e++) t2[e] = NEGF;
        s2 = 0.0f;
    }

    shfl_merge6<4>(t2);
#pragma unroll
    for (int off = 4; off >= 1; off >>= 1)
        s2 += __shfl_down_sync(0xffffffffu, s2, off);

    if (lane == 0) {
        const int kk = k < 1 ? 1 : (k > 5 ? 5 : k);   // mc index = kk within top-6
        float mc = t2[kk];
        const float tau = 0.5f * (1.0f + mc);
        float corr = 0.0f;
#pragma unroll
        for (int e = 0; e < 6; e++)
            if (t2[e] > tau) corr += 2.0f * t2[e] - mc - 1.0f;
        colv[w] = 2.0f * s2 - (float)NN * mc - corr - (float)NN * fmaxf(mc, 0.0f);
    }
    __syncthreads();

    if (w == 0) {
        float a = (lane < DD) ? colv[lane] : 0.0f;
#pragma unroll
        for (int off = 8; off >= 1; off >>= 1)
            a += __shfl_down_sync(0xffffffffu, a, off);
        if (lane == 0) {
            // C(k) = gamma - H_{k-1} + digamma(16) + 15/k (double-precomputed,
            // selected into a register, no memory access).
            float C = (k <= 1) ? 18.31822899f :
                      (k == 2) ?  9.81822899f :
                      (k == 3) ?  6.81822899f :
                      (k == 4) ?  5.23489566f :
                      (k == 5) ?  4.23489566f :
                                  3.53489566f;        // k >= 6
            out[0] = C + a * (1.0f / (float)NN);
        }
    }
}

extern "C" void kernel_launch(void* const* d_in, const int* in_sizes, int n_in,
                              void* d_out, int out_size) {
    // metadata order: x [N*D f32], k [1 i32] — pick by size to be robust.
    int xi = 0, ki = 1;
    if (n_in >= 2 && in_sizes[0] == 1) { xi = 1; ki = 0; }
    const float* x    = (const float*)d_in[xi];
    const int*   kptr = (const int*)d_in[ki];
    float*       out  = (float*)d_out;

    knn_entropy_kernel<<<NCTA, TPB>>>(x, kptr, out);
}